// round 6
// baseline (speedup 1.0000x reference)
#include <cuda_runtime.h>
#include <cuda_fp16.h>
#include <cstdint>

// Problem dims
static constexpr int MDIM = 8192;    // B*S
static constexpr int NDIM = 11008;   // OUT
static constexpr int KDIM = 4096;    // IN

// GEMM tiling (Ampere-style mma.sync path: compute_103 virtual arch has no tcgen05)
static constexpr int BM = 128;
static constexpr int BN = 256;
static constexpr int BK = 64;                 // 64 fp16 = 128B rows = SW128 atom
static constexpr int NCH = KDIM / BK;         // 64 K-chunks
static constexpr int STAGES = 3;

static constexpr int A_STAGE = BM * BK * 2;   // 16 KB
static constexpr int B_STAGE = BN * BK * 2;   // 32 KB
static constexpr int SM_A    = 0;
static constexpr int SM_B    = STAGES * A_STAGE;               // 49152
static constexpr int SM_BIAS = SM_B + STAGES * B_STAGE;        // 147456
static constexpr int SM_END  = SM_BIAS + BN * 4;               // 148480
static constexpr int DYN_SMEM = SM_END + 1024;                 // slack for 1KB align

// Scratch: fp16 copies of x and dequantized (q - zp) weights
__device__ __half g_xh[(size_t)MDIM * KDIM];
__device__ __half g_wh[(size_t)NDIM * KDIM];

// ---------------------------------------------------------------- helpers
__device__ __forceinline__ uint32_t smem_u32(const void* p) {
    uint32_t a;
    asm("{ .reg .u64 t; cvta.to.shared.u64 t, %1; cvt.u32.u64 %0, t; }"
        : "=r"(a) : "l"(p));
    return a;
}

__device__ __forceinline__ void cp_async16(uint32_t dst, const void* src) {
    asm volatile("cp.async.cg.shared.global [%0], [%1], 16;"
                 :: "r"(dst), "l"(src));
}
__device__ __forceinline__ void cp_commit() {
    asm volatile("cp.async.commit_group;" ::: "memory");
}
template <int N>
__device__ __forceinline__ void cp_wait() {
    asm volatile("cp.async.wait_group %0;" :: "n"(N) : "memory");
}

__device__ __forceinline__ void ldsm_x4(uint32_t* r, uint32_t addr) {
    asm volatile("ldmatrix.sync.aligned.m8n8.x4.shared.b16 {%0,%1,%2,%3}, [%4];"
                 : "=r"(r[0]), "=r"(r[1]), "=r"(r[2]), "=r"(r[3])
                 : "r"(addr));
}

__device__ __forceinline__ void mma16816(float* c, const uint32_t* a,
                                         uint32_t b0, uint32_t b1) {
    asm volatile(
        "mma.sync.aligned.m16n8k16.row.col.f32.f16.f16.f32 "
        "{%0,%1,%2,%3}, {%4,%5,%6,%7}, {%8,%9}, {%0,%1,%2,%3};"
        : "+f"(c[0]), "+f"(c[1]), "+f"(c[2]), "+f"(c[3])
        : "r"(a[0]), "r"(a[1]), "r"(a[2]), "r"(a[3]), "r"(b0), "r"(b1));
}

// ---------------------------------------------------------------- conversion
__global__ void cvt_x_kernel(const float* __restrict__ x) {
    size_t i = (size_t)blockIdx.x * blockDim.x + threadIdx.x;
    size_t n4 = (size_t)MDIM * KDIM / 4;
    if (i < n4) {
        float4 v = reinterpret_cast<const float4*>(x)[i];
        __half2* dst = reinterpret_cast<__half2*>(g_xh) + 2 * i;
        dst[0] = __floats2half2_rn(v.x, v.y);
        dst[1] = __floats2half2_rn(v.z, v.w);
    }
}

__global__ void cvt_w_kernel(const int* __restrict__ w4, const float* __restrict__ zp) {
    size_t i = (size_t)blockIdx.x * blockDim.x + threadIdx.x;
    size_t n4 = (size_t)NDIM * KDIM / 4;
    if (i < n4) {
        int4 q = reinterpret_cast<const int4*>(w4)[i];
        int z = __float2int_rn(zp[0]);   // zero_point is an exact integer
        __half2* dst = reinterpret_cast<__half2*>(g_wh) + 2 * i;
        dst[0] = __floats2half2_rn((float)(q.x - z), (float)(q.y - z));
        dst[1] = __floats2half2_rn((float)(q.z - z), (float)(q.w - z));
    }
}

// ---------------------------------------------------------------- GEMM
__global__ void __launch_bounds__(256, 1)
gemm_hmma_kernel(const float* __restrict__ scale, const float* __restrict__ bias,
                 float* __restrict__ out) {
    extern __shared__ char smem_raw[];
    char* sm = (char*)(((uintptr_t)smem_raw + 1023) & ~(uintptr_t)1023);
    uint32_t sb = smem_u32(sm);

    const int tid  = threadIdx.x;
    const int lane = tid & 31;
    const int wid  = tid >> 5;
    const int wm   = wid >> 2;        // 0..1  (M blocking: 64 rows per warp)
    const int wn   = wid & 3;         // 0..3  (N blocking: 64 cols per warp)
    const int m0   = blockIdx.y * BM;
    const int n0   = blockIdx.x * BN;

    // bias tile -> smem (256 threads, 256 values)
    ((float*)(sm + SM_BIAS))[tid] = bias[n0 + tid];

    // ---- per-thread cp.async descriptors (SW128 swizzle) ----
    // For v = tid + i*256: seg s = tid & 7 (constant), row r = (tid>>3) + 32*i.
    const int  seg   = tid & 7;
    const int  rbase = tid >> 3;
    const uint32_t swz = (uint32_t)((seg * 16) ^ ((rbase & 7) << 4)); // (r&7) invariant in i
    const char* gA = (const char*)(g_xh + (size_t)m0 * KDIM);
    const char* gB = (const char*)(g_wh + (size_t)n0 * KDIM);

    // ---- ldmatrix lane addressing ----
    // lane row within a 16-row block = lane & 15; col16 select = lane>>4.
    // XOR mask reduces to lane-constant (lane&7)<<4 since row blocks are 16-aligned.
    uint32_t cks[4];
#pragma unroll
    for (int ks = 0; ks < 4; ks++)
        cks[ks] = (uint32_t)((((lane >> 4) * 16) + ks * 32) ^ ((lane & 7) << 4));
    const uint32_t arow = (uint32_t)((wm * 64 + (lane & 15)) * 128);
    const uint32_t brow = (uint32_t)((wn * 64 + (lane & 15)) * 128);

    float c[4][8][4];
#pragma unroll
    for (int mi = 0; mi < 4; mi++)
#pragma unroll
        for (int ni = 0; ni < 8; ni++)
#pragma unroll
            for (int r = 0; r < 4; r++) c[mi][ni][r] = 0.0f;

    // ---- stage loader ----
    auto issue_stage = [&](int st, int kc) {
        uint32_t ab = sb + SM_A + st * A_STAGE;
        uint32_t bb = sb + SM_B + st * B_STAGE;
        const char* srcA = gA + (size_t)kc * (BK * 2);
        const char* srcB = gB + (size_t)kc * (BK * 2);
#pragma unroll
        for (int i = 0; i < 4; i++) {          // A: 128 rows x 8 segs
            int r = rbase + 32 * i;
            cp_async16(ab + (uint32_t)(r * 128) + swz,
                       srcA + (size_t)r * (KDIM * 2) + seg * 16);
        }
#pragma unroll
        for (int i = 0; i < 8; i++) {          // B: 256 rows x 8 segs
            int r = rbase + 32 * i;
            cp_async16(bb + (uint32_t)(r * 128) + swz,
                       srcB + (size_t)r * (KDIM * 2) + seg * 16);
        }
    };

    // ---- prologue: stages 0,1 in flight ----
    issue_stage(0, 0); cp_commit();
    issue_stage(1, 1); cp_commit();

    // ---- main loop ----
    for (int k = 0; k < NCH; ++k) {
        __syncthreads();                       // everyone done reading stage (k-1)%3
        if (k + 2 < NCH) issue_stage((k + 2) % STAGES, k + 2);
        cp_commit();                           // uniform group count (empty ok)
        cp_wait<2>();                          // stage k landed
        __syncthreads();                       // cross-thread visibility

        const uint32_t ab = sb + SM_A + (k % STAGES) * A_STAGE + arow;
        const uint32_t bb = sb + SM_B + (k % STAGES) * B_STAGE + brow;

#pragma unroll
        for (int ks = 0; ks < 4; ks++) {       // four k16 steps per BK=64 chunk
            uint32_t a[4][4];
#pragma unroll
            for (int mi = 0; mi < 4; mi++)
                ldsm_x4(a[mi], ab + mi * 2048 + cks[ks]);

            uint32_t bf[4][4];                 // each x4 covers n16 x k16
#pragma unroll
            for (int nj = 0; nj < 4; nj++)
                ldsm_x4(bf[nj], bb + nj * 2048 + cks[ks]);

#pragma unroll
            for (int mi = 0; mi < 4; mi++)
#pragma unroll
                for (int nj = 0; nj < 4; nj++) {
                    mma16816(c[mi][2 * nj + 0], a[mi], bf[nj][0], bf[nj][2]);
                    mma16816(c[mi][2 * nj + 1], a[mi], bf[nj][1], bf[nj][3]);
                }
        }
    }

    // ---- epilogue: out = scale*acc + bias ----
    const float sc = *scale;
    const float* bsm = (const float*)(sm + SM_BIAS);
    const int qrow = lane >> 2;                // 0..7
    const int qcol = 2 * (lane & 3);           // 0,2,4,6
#pragma unroll
    for (int mi = 0; mi < 4; mi++) {
        const size_t mlo = (size_t)(m0 + wm * 64 + mi * 16 + qrow);
#pragma unroll
        for (int ni = 0; ni < 8; ni++) {
            const int nc = wn * 64 + ni * 8 + qcol;
            const float b0 = bsm[nc], b1 = bsm[nc + 1];
            float2 v0, v1;
            v0.x = fmaf(sc, c[mi][ni][0], b0);
            v0.y = fmaf(sc, c[mi][ni][1], b1);
            v1.x = fmaf(sc, c[mi][ni][2], b0);
            v1.y = fmaf(sc, c[mi][ni][3], b1);
            *reinterpret_cast<float2*>(out + mlo * NDIM + n0 + nc)       = v0;
            *reinterpret_cast<float2*>(out + (mlo + 8) * NDIM + n0 + nc) = v1;
        }
    }
}

// ---------------------------------------------------------------- launch
extern "C" void kernel_launch(void* const* d_in, const int* in_sizes, int n_in,
                              void* d_out, int out_size) {
    const float* x     = (const float*)d_in[0];
    const int*   w4    = (const int*)d_in[1];
    const float* scale = (const float*)d_in[2];
    const float* zp    = (const float*)d_in[3];
    const float* bias  = (const float*)d_in[4];
    float* out = (float*)d_out;

    cudaFuncSetAttribute(gemm_hmma_kernel,
                         cudaFuncAttributeMaxDynamicSharedMemorySize, DYN_SMEM);

    {
        long n4 = (long)MDIM * KDIM / 4;
        cvt_x_kernel<<<(int)((n4 + 255) / 256), 256>>>(x);
    }
    {
        long n4 = (long)NDIM * KDIM / 4;
        cvt_w_kernel<<<(int)((n4 + 255) / 256), 256>>>(w4, zp);
    }
    dim3 grid(NDIM / BN, MDIM / BM);   // 43 x 64
    gemm_hmma_kernel<<<grid, 256, DYN_SMEM>>>(scale, bias, out);
}

// round 9
// speedup vs baseline: 1.0231x; 1.0231x over previous
#include <cuda_runtime.h>
#include <cuda_fp16.h>
#include <cstdint>

// Problem dims
static constexpr int MDIM = 8192;    // B*S
static constexpr int NDIM = 11008;   // OUT
static constexpr int KDIM = 4096;    // IN

// GEMM tiling (mma.sync path: compute_103 virtual arch rejects tcgen05)
static constexpr int BM = 128;
static constexpr int BN = 256;
static constexpr int BK = 64;                 // 64 fp16 = 128B rows = SW128 atom
static constexpr int NCH = KDIM / BK;         // 64 K-chunks
static constexpr int STAGES = 4;

static constexpr int A_STAGE = BM * BK * 2;   // 16 KB
static constexpr int B_STAGE = BN * BK * 2;   // 32 KB
static constexpr int SM_A    = 0;
static constexpr int SM_B    = STAGES * A_STAGE;               // 65536
static constexpr int SM_BIAS = SM_B + STAGES * B_STAGE;        // 196608
static constexpr int SM_END  = SM_BIAS + BN * 4;               // 197632
static constexpr int DYN_SMEM = SM_END + 1024;                 // align slack

// Scratch: fp16 copies of x and dequantized (q - zp) weights
__device__ __half g_xh[(size_t)MDIM * KDIM];
__device__ __half g_wh[(size_t)NDIM * KDIM];

// ---------------------------------------------------------------- helpers
__device__ __forceinline__ uint32_t smem_u32(const void* p) {
    uint32_t a;
    asm("{ .reg .u64 t; cvta.to.shared.u64 t, %1; cvt.u32.u64 %0, t; }"
        : "=r"(a) : "l"(p));
    return a;
}

__device__ __forceinline__ void cp_async16(uint32_t dst, const void* src) {
    asm volatile("cp.async.cg.shared.global [%0], [%1], 16;"
                 :: "r"(dst), "l"(src));
}
__device__ __forceinline__ void cp_commit() {
    asm volatile("cp.async.commit_group;" ::: "memory");
}
template <int N>
__device__ __forceinline__ void cp_wait() {
    asm volatile("cp.async.wait_group %0;" :: "n"(N) : "memory");
}

__device__ __forceinline__ void ldsm_x4(uint32_t* r, uint32_t addr) {
    asm volatile("ldmatrix.sync.aligned.m8n8.x4.shared.b16 {%0,%1,%2,%3}, [%4];"
                 : "=r"(r[0]), "=r"(r[1]), "=r"(r[2]), "=r"(r[3])
                 : "r"(addr));
}

__device__ __forceinline__ void mma16816(float* c, const uint32_t* a,
                                         uint32_t b0, uint32_t b1) {
    asm volatile(
        "mma.sync.aligned.m16n8k16.row.col.f32.f16.f16.f32 "
        "{%0,%1,%2,%3}, {%4,%5,%6,%7}, {%8,%9}, {%0,%1,%2,%3};"
        : "+f"(c[0]), "+f"(c[1]), "+f"(c[2]), "+f"(c[3])
        : "r"(a[0]), "r"(a[1]), "r"(a[2]), "r"(a[3]), "r"(b0), "r"(b1));
}

// ---------------------------------------------------------------- conversion
__global__ void cvt_x_kernel(const float* __restrict__ x) {
    size_t i = (size_t)blockIdx.x * blockDim.x + threadIdx.x;
    size_t n4 = (size_t)MDIM * KDIM / 4;
    if (i < n4) {
        float4 v = reinterpret_cast<const float4*>(x)[i];
        __half2* dst = reinterpret_cast<__half2*>(g_xh) + 2 * i;
        dst[0] = __floats2half2_rn(v.x, v.y);
        dst[1] = __floats2half2_rn(v.z, v.w);
    }
}

__global__ void cvt_w_kernel(const int* __restrict__ w4, const float* __restrict__ zp) {
    size_t i = (size_t)blockIdx.x * blockDim.x + threadIdx.x;
    size_t n4 = (size_t)NDIM * KDIM / 4;
    if (i < n4) {
        int4 q = reinterpret_cast<const int4*>(w4)[i];
        int z = __float2int_rn(zp[0]);   // zero_point is an exact integer
        __half2* dst = reinterpret_cast<__half2*>(g_wh) + 2 * i;
        dst[0] = __floats2half2_rn((float)(q.x - z), (float)(q.y - z));
        dst[1] = __floats2half2_rn((float)(q.z - z), (float)(q.w - z));
    }
}

// ---------------------------------------------------------------- GEMM
__global__ void __launch_bounds__(256, 1)
gemm_hmma_kernel(const float* __restrict__ scale, const float* __restrict__ bias,
                 float* __restrict__ out) {
    extern __shared__ char smem_raw[];
    char* sm = (char*)(((uintptr_t)smem_raw + 1023) & ~(uintptr_t)1023);
    uint32_t sb = smem_u32(sm);

    const int tid  = threadIdx.x;
    const int lane = tid & 31;
    const int wid  = tid >> 5;
    const int wm   = wid >> 2;        // 0..1  (64 M-rows per warp)
    const int wn   = wid & 3;         // 0..3  (64 N-cols per warp)
    const int m0   = blockIdx.y * BM;
    const int n0   = blockIdx.x * BN;

    // bias tile -> smem (256 threads, 256 values)
    ((float*)(sm + SM_BIAS))[tid] = bias[n0 + tid];

    // ---- per-thread cp.async addressing (SW128 swizzle) ----
    const int  seg   = tid & 7;
    const int  rbase = tid >> 3;
    const uint32_t swz = (uint32_t)((seg * 16) ^ ((rbase & 7) << 4));
    const char* gA = (const char*)(g_xh + (size_t)m0 * KDIM);
    const char* gB = (const char*)(g_wh + (size_t)n0 * KDIM);

    // ---- ldmatrix lane addressing ----
    uint32_t cks[4];
#pragma unroll
    for (int ks = 0; ks < 4; ks++)
        cks[ks] = (uint32_t)((((lane >> 4) * 16) + ks * 32) ^ ((lane & 7) << 4));
    const uint32_t arow = (uint32_t)((wm * 64 + (lane & 15)) * 128);
    const uint32_t brow = (uint32_t)((wn * 64 + (lane & 15)) * 128);

    float c[4][8][4];
#pragma unroll
    for (int mi = 0; mi < 4; mi++)
#pragma unroll
        for (int ni = 0; ni < 8; ni++)
#pragma unroll
            for (int r = 0; r < 4; r++) c[mi][ni][r] = 0.0f;

    auto issue_stage = [&](int st, int kc) {
        uint32_t ab = sb + SM_A + st * A_STAGE;
        uint32_t bb = sb + SM_B + st * B_STAGE;
        const char* srcA = gA + (size_t)kc * (BK * 2);
        const char* srcB = gB + (size_t)kc * (BK * 2);
#pragma unroll
        for (int i = 0; i < 4; i++) {          // A: 128 rows x 8 segs
            int r = rbase + 32 * i;
            cp_async16(ab + (uint32_t)(r * 128) + swz,
                       srcA + (size_t)r * (KDIM * 2) + seg * 16);
        }
#pragma unroll
        for (int i = 0; i < 8; i++) {          // B: 256 rows x 8 segs
            int r = rbase + 32 * i;
            cp_async16(bb + (uint32_t)(r * 128) + swz,
                       srcB + (size_t)r * (KDIM * 2) + seg * 16);
        }
    };

    // ---- prologue: 3 stages in flight ----
    issue_stage(0, 0); cp_commit();
    issue_stage(1, 1); cp_commit();
    issue_stage(2, 2); cp_commit();

    // ---- main loop: ONE barrier per chunk (4-deep ring makes it safe:
    // stage written at iter k is (k+3)%4 == (k-1)%4, last read in iter k-1,
    // which every thread finished before this iteration's barrier). ----
    for (int k = 0; k < NCH; ++k) {
        cp_wait<2>();                          // stage k landed (3 pending -> 2)
        __syncthreads();                       // visibility + ring-reuse safety
        if (k + 3 < NCH) issue_stage((k + 3) % STAGES, k + 3);
        cp_commit();                           // uniform group count

        const uint32_t ab = sb + SM_A + (k % STAGES) * A_STAGE + arow;
        const uint32_t bb = sb + SM_B + (k % STAGES) * B_STAGE + brow;

        // fragment double-buffer: LDSM for step s+1 overlaps MMAs of step s
        uint32_t a[2][4][4], bf[2][4][4];
#pragma unroll
        for (int mi = 0; mi < 4; mi++) ldsm_x4(a[0][mi], ab + mi * 2048 + cks[0]);
#pragma unroll
        for (int nj = 0; nj < 4; nj++) ldsm_x4(bf[0][nj], bb + nj * 2048 + cks[0]);

#pragma unroll
        for (int ks = 0; ks < 4; ks++) {
            const int cur = ks & 1, nxt = cur ^ 1;
            if (ks < 3) {
#pragma unroll
                for (int mi = 0; mi < 4; mi++)
                    ldsm_x4(a[nxt][mi], ab + mi * 2048 + cks[ks + 1]);
#pragma unroll
                for (int nj = 0; nj < 4; nj++)
                    ldsm_x4(bf[nxt][nj], bb + nj * 2048 + cks[ks + 1]);
            }
#pragma unroll
            for (int mi = 0; mi < 4; mi++)
#pragma unroll
                for (int nj = 0; nj < 4; nj++) {
                    mma16816(c[mi][2 * nj + 0], a[cur][mi], bf[cur][nj][0], bf[cur][nj][2]);
                    mma16816(c[mi][2 * nj + 1], a[cur][mi], bf[cur][nj][1], bf[cur][nj][3]);
                }
        }
    }

    // ---- epilogue: out = scale*acc + bias ----
    const float sc = *scale;
    const float* bsm = (const float*)(sm + SM_BIAS);
    const int qrow = lane >> 2;
    const int qcol = 2 * (lane & 3);
#pragma unroll
    for (int mi = 0; mi < 4; mi++) {
        const size_t mlo = (size_t)(m0 + wm * 64 + mi * 16 + qrow);
#pragma unroll
        for (int ni = 0; ni < 8; ni++) {
            const int nc = wn * 64 + ni * 8 + qcol;
            const float b0 = bsm[nc], b1 = bsm[nc + 1];
            float2 v0, v1;
            v0.x = fmaf(sc, c[mi][ni][0], b0);
            v0.y = fmaf(sc, c[mi][ni][1], b1);
            v1.x = fmaf(sc, c[mi][ni][2], b0);
            v1.y = fmaf(sc, c[mi][ni][3], b1);
            *reinterpret_cast<float2*>(out + mlo * NDIM + n0 + nc)       = v0;
            *reinterpret_cast<float2*>(out + (mlo + 8) * NDIM + n0 + nc) = v1;
        }
    }
}

// ---------------------------------------------------------------- launch
extern "C" void kernel_launch(void* const* d_in, const int* in_sizes, int n_in,
                              void* d_out, int out_size) {
    const float* x     = (const float*)d_in[0];
    const int*   w4    = (const int*)d_in[1];
    const float* scale = (const float*)d_in[2];
    const float* zp    = (const float*)d_in[3];
    const float* bias  = (const float*)d_in[4];
    float* out = (float*)d_out;

    cudaFuncSetAttribute(gemm_hmma_kernel,
                         cudaFuncAttributeMaxDynamicSharedMemorySize, DYN_SMEM);

    {
        long n4 = (long)MDIM * KDIM / 4;
        cvt_x_kernel<<<(int)((n4 + 255) / 256), 256>>>(x);
    }
    {
        long n4 = (long)NDIM * KDIM / 4;
        cvt_w_kernel<<<(int)((n4 + 255) / 256), 256>>>(w4, zp);
    }
    dim3 grid(NDIM / BN, MDIM / BM);   // 43 x 64
    gemm_hmma_kernel<<<grid, 256, DYN_SMEM>>>(scale, bias, out);
}

// round 10
// speedup vs baseline: 1.0954x; 1.0707x over previous
#include <cuda_runtime.h>
#include <cuda_fp16.h>
#include <cstdint>

// Problem dims
static constexpr int MDIM = 8192;    // B*S
static constexpr int NDIM = 11008;   // OUT
static constexpr int KDIM = 4096;    // IN

// GEMM tiling (mma.sync path: compute_103 virtual arch rejects tcgen05)
static constexpr int BM = 128;
static constexpr int BN = 128;
static constexpr int BK = 64;                 // 64 fp16 = 128B rows = SW128 atom
static constexpr int NCH = KDIM / BK;         // 64 K-chunks
static constexpr int STAGES = 3;
static constexpr int NTHREADS = 128;          // 4 warps, warp tile 64x64

static constexpr int A_STAGE = BM * BK * 2;   // 16 KB
static constexpr int B_STAGE = BN * BK * 2;   // 16 KB
static constexpr int SM_A    = 0;
static constexpr int SM_B    = STAGES * A_STAGE;               // 49152
static constexpr int SM_BIAS = SM_B + STAGES * B_STAGE;        // 98304
static constexpr int SM_END  = SM_BIAS + BN * 4;               // 98816
static constexpr int DYN_SMEM = SM_END + 1024;                 // align slack (~97.5KB)

static constexpr int GRID_M = MDIM / BM;      // 64
static constexpr int GRID_N = NDIM / BN;      // 86
static constexpr int GROUP_M = 8;             // L2 tile-swizzle panel height

// Scratch: fp16 copies of x and dequantized (q - zp) weights
__device__ __half g_xh[(size_t)MDIM * KDIM];
__device__ __half g_wh[(size_t)NDIM * KDIM];

// ---------------------------------------------------------------- helpers
__device__ __forceinline__ uint32_t smem_u32(const void* p) {
    uint32_t a;
    asm("{ .reg .u64 t; cvta.to.shared.u64 t, %1; cvt.u32.u64 %0, t; }"
        : "=r"(a) : "l"(p));
    return a;
}

__device__ __forceinline__ void cp_async16(uint32_t dst, const void* src) {
    asm volatile("cp.async.cg.shared.global [%0], [%1], 16;"
                 :: "r"(dst), "l"(src));
}
__device__ __forceinline__ void cp_commit() {
    asm volatile("cp.async.commit_group;" ::: "memory");
}
template <int N>
__device__ __forceinline__ void cp_wait() {
    asm volatile("cp.async.wait_group %0;" :: "n"(N) : "memory");
}

__device__ __forceinline__ void ldsm_x4(uint32_t* r, uint32_t addr) {
    asm volatile("ldmatrix.sync.aligned.m8n8.x4.shared.b16 {%0,%1,%2,%3}, [%4];"
                 : "=r"(r[0]), "=r"(r[1]), "=r"(r[2]), "=r"(r[3])
                 : "r"(addr));
}

__device__ __forceinline__ void mma16816(float* c, const uint32_t* a,
                                         uint32_t b0, uint32_t b1) {
    asm volatile(
        "mma.sync.aligned.m16n8k16.row.col.f32.f16.f16.f32 "
        "{%0,%1,%2,%3}, {%4,%5,%6,%7}, {%8,%9}, {%0,%1,%2,%3};"
        : "+f"(c[0]), "+f"(c[1]), "+f"(c[2]), "+f"(c[3])
        : "r"(a[0]), "r"(a[1]), "r"(a[2]), "r"(a[3]), "r"(b0), "r"(b1));
}

// ---------------------------------------------------------------- conversion
__global__ void cvt_x_kernel(const float* __restrict__ x) {
    size_t i = (size_t)blockIdx.x * blockDim.x + threadIdx.x;
    size_t n4 = (size_t)MDIM * KDIM / 4;
    if (i < n4) {
        float4 v = reinterpret_cast<const float4*>(x)[i];
        __half2* dst = reinterpret_cast<__half2*>(g_xh) + 2 * i;
        dst[0] = __floats2half2_rn(v.x, v.y);
        dst[1] = __floats2half2_rn(v.z, v.w);
    }
}

__global__ void cvt_w_kernel(const int* __restrict__ w4, const float* __restrict__ zp) {
    size_t i = (size_t)blockIdx.x * blockDim.x + threadIdx.x;
    size_t n4 = (size_t)NDIM * KDIM / 4;
    if (i < n4) {
        int4 q = reinterpret_cast<const int4*>(w4)[i];
        int z = __float2int_rn(zp[0]);   // zero_point is an exact integer
        __half2* dst = reinterpret_cast<__half2*>(g_wh) + 2 * i;
        dst[0] = __floats2half2_rn((float)(q.x - z), (float)(q.y - z));
        dst[1] = __floats2half2_rn((float)(q.z - z), (float)(q.w - z));
    }
}

// ---------------------------------------------------------------- GEMM
__global__ void __launch_bounds__(NTHREADS, 2)
gemm_hmma_kernel(const float* __restrict__ scale, const float* __restrict__ bias,
                 float* __restrict__ out) {
    extern __shared__ char smem_raw[];
    char* sm = (char*)(((uintptr_t)smem_raw + 1023) & ~(uintptr_t)1023);
    uint32_t sb = smem_u32(sm);

    const int tid  = threadIdx.x;
    const int lane = tid & 31;
    const int wid  = tid >> 5;        // 0..3
    const int wm   = wid >> 1;        // 0..1  (64 M-rows per warp)
    const int wn   = wid & 1;         // 0..1  (64 N-cols per warp)

    // ---- CTA tile swizzle: GROUP_M-high panels for L2 reuse ----
    const int cid   = blockIdx.x;
    const int per_p = GROUP_M * GRID_N;
    const int panel = cid / per_p;
    const int rem   = cid - panel * per_p;
    const int bm    = panel * GROUP_M + (rem % GROUP_M);
    const int bn    = rem / GROUP_M;
    const int m0 = bm * BM;
    const int n0 = bn * BN;

    // bias tile -> smem (128 threads, 128 values)
    ((float*)(sm + SM_BIAS))[tid] = bias[n0 + tid];

    // ---- per-thread cp.async addressing (SW128 swizzle) ----
    const int  seg   = tid & 7;
    const int  rbase = tid >> 3;      // 0..15
    const uint32_t swz = (uint32_t)((seg * 16) ^ ((rbase & 7) << 4)); // (r&7) invariant, 16|stride
    const char* gA = (const char*)(g_xh + (size_t)m0 * KDIM);
    const char* gB = (const char*)(g_wh + (size_t)n0 * KDIM);

    // ---- ldmatrix lane addressing ----
    uint32_t cks[4];
#pragma unroll
    for (int ks = 0; ks < 4; ks++)
        cks[ks] = (uint32_t)((((lane >> 4) * 16) + ks * 32) ^ ((lane & 7) << 4));
    const uint32_t arow = (uint32_t)((wm * 64 + (lane & 15)) * 128);
    const uint32_t brow = (uint32_t)((wn * 64 + (lane & 15)) * 128);

    float c[4][8][4];
#pragma unroll
    for (int mi = 0; mi < 4; mi++)
#pragma unroll
        for (int ni = 0; ni < 8; ni++)
#pragma unroll
            for (int r = 0; r < 4; r++) c[mi][ni][r] = 0.0f;

    auto issue_stage = [&](int st, int kc) {
        uint32_t ab = sb + SM_A + st * A_STAGE;
        uint32_t bb = sb + SM_B + st * B_STAGE;
        const char* srcA = gA + (size_t)kc * (BK * 2);
        const char* srcB = gB + (size_t)kc * (BK * 2);
#pragma unroll
        for (int i = 0; i < 8; i++) {          // A: 128 rows x 8 segs / 128 thr
            int r = rbase + 16 * i;
            cp_async16(ab + (uint32_t)(r * 128) + swz,
                       srcA + (size_t)r * (KDIM * 2) + seg * 16);
        }
#pragma unroll
        for (int i = 0; i < 8; i++) {          // B: 128 rows x 8 segs / 128 thr
            int r = rbase + 16 * i;
            cp_async16(bb + (uint32_t)(r * 128) + swz,
                       srcB + (size_t)r * (KDIM * 2) + seg * 16);
        }
    };

    // ---- prologue: fill the ring ----
    issue_stage(0, 0); cp_commit();
    issue_stage(1, 1); cp_commit();

    // ---- main loop: one barrier per chunk. Ring safety: stage written at
    // iter k is (k+2)%3 == (k-1)%3, last read at iter k-1, finished before
    // this iteration's barrier. ----
    for (int k = 0; k < NCH; ++k) {
        cp_wait<1>();                          // stage k landed (2 pending -> 1)
        __syncthreads();                       // cross-thread visibility + reuse

        const uint32_t ab = sb + SM_A + (k % STAGES) * A_STAGE + arow;
        const uint32_t bb = sb + SM_B + (k % STAGES) * B_STAGE + brow;

        // preload step-0 fragments, then kick next stage's cp.async
        uint32_t a[2][4][4], bf[2][4][4];
#pragma unroll
        for (int mi = 0; mi < 4; mi++) ldsm_x4(a[0][mi], ab + mi * 2048 + cks[0]);
#pragma unroll
        for (int nj = 0; nj < 4; nj++) ldsm_x4(bf[0][nj], bb + nj * 2048 + cks[0]);

        if (k + 2 < NCH) issue_stage((k + 2) % STAGES, k + 2);
        cp_commit();                           // uniform group count

#pragma unroll
        for (int ks = 0; ks < 4; ks++) {
            const int cur = ks & 1, nxt = cur ^ 1;
            if (ks < 3) {
#pragma unroll
                for (int mi = 0; mi < 4; mi++)
                    ldsm_x4(a[nxt][mi], ab + mi * 2048 + cks[ks + 1]);
#pragma unroll
                for (int nj = 0; nj < 4; nj++)
                    ldsm_x4(bf[nxt][nj], bb + nj * 2048 + cks[ks + 1]);
            }
#pragma unroll
            for (int mi = 0; mi < 4; mi++)
#pragma unroll
                for (int nj = 0; nj < 4; nj++) {
                    mma16816(c[mi][2 * nj + 0], a[cur][mi], bf[cur][nj][0], bf[cur][nj][2]);
                    mma16816(c[mi][2 * nj + 1], a[cur][mi], bf[cur][nj][1], bf[cur][nj][3]);
                }
        }
    }

    // ---- epilogue: out = scale*acc + bias ----
    const float sc = *scale;
    const float* bsm = (const float*)(sm + SM_BIAS);
    const int qrow = lane >> 2;
    const int qcol = 2 * (lane & 3);
#pragma unroll
    for (int mi = 0; mi < 4; mi++) {
        const size_t mlo = (size_t)(m0 + wm * 64 + mi * 16 + qrow);
#pragma unroll
        for (int ni = 0; ni < 8; ni++) {
            const int nc = wn * 64 + ni * 8 + qcol;
            const float b0 = bsm[nc], b1 = bsm[nc + 1];
            float2 v0, v1;
            v0.x = fmaf(sc, c[mi][ni][0], b0);
            v0.y = fmaf(sc, c[mi][ni][1], b1);
            v1.x = fmaf(sc, c[mi][ni][2], b0);
            v1.y = fmaf(sc, c[mi][ni][3], b1);
            *reinterpret_cast<float2*>(out + mlo * NDIM + n0 + nc)       = v0;
            *reinterpret_cast<float2*>(out + (mlo + 8) * NDIM + n0 + nc) = v1;
        }
    }
}

// ---------------------------------------------------------------- launch
extern "C" void kernel_launch(void* const* d_in, const int* in_sizes, int n_in,
                              void* d_out, int out_size) {
    const float* x     = (const float*)d_in[0];
    const int*   w4    = (const int*)d_in[1];
    const float* scale = (const float*)d_in[2];
    const float* zp    = (const float*)d_in[3];
    const float* bias  = (const float*)d_in[4];
    float* out = (float*)d_out;

    cudaFuncSetAttribute(gemm_hmma_kernel,
                         cudaFuncAttributeMaxDynamicSharedMemorySize, DYN_SMEM);

    {
        long n4 = (long)MDIM * KDIM / 4;
        cvt_x_kernel<<<(int)((n4 + 255) / 256), 256>>>(x);
    }
    {
        long n4 = (long)NDIM * KDIM / 4;
        cvt_w_kernel<<<(int)((n4 + 255) / 256), 256>>>(w4, zp);
    }
    gemm_hmma_kernel<<<GRID_M * GRID_N, NTHREADS, DYN_SMEM>>>(scale, bias, out);
}

// round 13
// speedup vs baseline: 1.0993x; 1.0035x over previous
#include <cuda_runtime.h>
#include <cuda_fp16.h>
#include <cstdint>

// Problem dims
static constexpr int MDIM = 8192;    // B*S
static constexpr int NDIM = 11008;   // OUT
static constexpr int KDIM = 4096;    // IN

// GEMM tiling (mma.sync path: harness assembles via .target sm_103 -> no tcgen05)
static constexpr int BM = 128;
static constexpr int BN = 128;
static constexpr int BK = 64;                 // 64 fp16 = 128B rows = SW128 atom
static constexpr int NCH = KDIM / BK;         // 64 K-chunks
static constexpr int STAGES = 3;
static constexpr int NTHREADS = 128;          // 4 warps, warp tile 64x64

static constexpr int A_STAGE = BM * BK * 2;   // 16 KB
static constexpr int B_STAGE = BN * BK * 2;   // 16 KB
static constexpr int SM_A    = 0;
static constexpr int SM_B    = STAGES * A_STAGE;               // 49152
static constexpr int SM_BIAS = SM_B + STAGES * B_STAGE;        // 98304
static constexpr int SM_END  = SM_BIAS + BN * 4;               // 98816
static constexpr int DYN_SMEM = SM_END + 1024;                 // ~97.5KB -> 2 CTAs/SM

static constexpr int GRID_M = MDIM / BM;      // 64
static constexpr int GRID_N = NDIM / BN;      // 86
static constexpr int GROUP_M = 8;             // L2 tile-swizzle panel height

// Scratch: fp16 copies of x and dequantized (q - zp) weights
__device__ __half g_xh[(size_t)MDIM * KDIM];
__device__ __half g_wh[(size_t)NDIM * KDIM];

// ---------------------------------------------------------------- helpers
__device__ __forceinline__ uint32_t smem_u32(const void* p) {
    uint32_t a;
    asm("{ .reg .u64 t; cvta.to.shared.u64 t, %1; cvt.u32.u64 %0, t; }"
        : "=r"(a) : "l"(p));
    return a;
}

__device__ __forceinline__ uint32_t h2_bits(__half2 h) {
    union { __half2 h2; uint32_t u; } cvt;
    cvt.h2 = h;
    return cvt.u;
}

// cp.async with L2 prefetch hint: pulls the adjacent sector for streaming rows
__device__ __forceinline__ void cp_async16(uint32_t dst, const void* src) {
    asm volatile("cp.async.cg.shared.global.L2::256B [%0], [%1], 16;"
                 :: "r"(dst), "l"(src));
}
__device__ __forceinline__ void cp_commit() {
    asm volatile("cp.async.commit_group;" ::: "memory");
}
template <int N>
__device__ __forceinline__ void cp_wait() {
    asm volatile("cp.async.wait_group %0;" :: "n"(N) : "memory");
}

__device__ __forceinline__ void ldsm_x4(uint32_t* r, uint32_t addr) {
    asm volatile("ldmatrix.sync.aligned.m8n8.x4.shared.b16 {%0,%1,%2,%3}, [%4];"
                 : "=r"(r[0]), "=r"(r[1]), "=r"(r[2]), "=r"(r[3])
                 : "r"(addr));
}

__device__ __forceinline__ void mma16816(float* c, const uint32_t* a,
                                         uint32_t b0, uint32_t b1) {
    asm volatile(
        "mma.sync.aligned.m16n8k16.row.col.f32.f16.f16.f32 "
        "{%0,%1,%2,%3}, {%4,%5,%6,%7}, {%8,%9}, {%0,%1,%2,%3};"
        : "+f"(c[0]), "+f"(c[1]), "+f"(c[2]), "+f"(c[3])
        : "r"(a[0]), "r"(a[1]), "r"(a[2]), "r"(a[3]), "r"(b0), "r"(b1));
}

// ---------------------------------------------------------------- conversion
// 8 elems/thread, 16B loads *and* 16B stores for full DRAM sector efficiency
__global__ void cvt_x_kernel(const float* __restrict__ x) {
    size_t i = (size_t)blockIdx.x * blockDim.x + threadIdx.x;
    size_t n8 = (size_t)MDIM * KDIM / 8;
    if (i < n8) {
        float4 v0 = reinterpret_cast<const float4*>(x)[2 * i + 0];
        float4 v1 = reinterpret_cast<const float4*>(x)[2 * i + 1];
        uint4 o;
        o.x = h2_bits(__floats2half2_rn(v0.x, v0.y));
        o.y = h2_bits(__floats2half2_rn(v0.z, v0.w));
        o.z = h2_bits(__floats2half2_rn(v1.x, v1.y));
        o.w = h2_bits(__floats2half2_rn(v1.z, v1.w));
        reinterpret_cast<uint4*>(g_xh)[i] = o;
    }
}

__global__ void cvt_w_kernel(const int* __restrict__ w4, const float* __restrict__ zp) {
    size_t i = (size_t)blockIdx.x * blockDim.x + threadIdx.x;
    size_t n8 = (size_t)NDIM * KDIM / 8;
    if (i < n8) {
        int4 q0 = reinterpret_cast<const int4*>(w4)[2 * i + 0];
        int4 q1 = reinterpret_cast<const int4*>(w4)[2 * i + 1];
        int z = __float2int_rn(zp[0]);   // zero_point is an exact integer
        uint4 o;
        o.x = h2_bits(__floats2half2_rn((float)(q0.x - z), (float)(q0.y - z)));
        o.y = h2_bits(__floats2half2_rn((float)(q0.z - z), (float)(q0.w - z)));
        o.z = h2_bits(__floats2half2_rn((float)(q1.x - z), (float)(q1.y - z)));
        o.w = h2_bits(__floats2half2_rn((float)(q1.z - z), (float)(q1.w - z)));
        reinterpret_cast<uint4*>(g_wh)[i] = o;
    }
}

// ---------------------------------------------------------------- GEMM
__global__ void __launch_bounds__(NTHREADS, 2)
gemm_hmma_kernel(const float* __restrict__ scale, const float* __restrict__ bias,
                 float* __restrict__ out) {
    extern __shared__ char smem_raw[];
    char* sm = (char*)(((uintptr_t)smem_raw + 1023) & ~(uintptr_t)1023);
    uint32_t sb = smem_u32(sm);

    const int tid  = threadIdx.x;
    const int lane = tid & 31;
    const int wid  = tid >> 5;        // 0..3
    const int wm   = wid >> 1;        // 0..1  (64 M-rows per warp)
    const int wn   = wid & 1;         // 0..1  (64 N-cols per warp)

    // ---- CTA tile swizzle: GROUP_M-high panels for L2 reuse ----
    const int cid   = blockIdx.x;
    const int per_p = GROUP_M * GRID_N;
    const int panel = cid / per_p;
    const int rem   = cid - panel * per_p;
    const int bm    = panel * GROUP_M + (rem % GROUP_M);
    const int bn    = rem / GROUP_M;
    const int m0 = bm * BM;
    const int n0 = bn * BN;

    // bias tile -> smem (128 threads, 128 values)
    ((float*)(sm + SM_BIAS))[tid] = bias[n0 + tid];

    // ---- per-thread cp.async addressing (SW128 swizzle) ----
    const int  seg   = tid & 7;
    const int  rbase = tid >> 3;      // 0..15
    const uint32_t swz = (uint32_t)((seg * 16) ^ ((rbase & 7) << 4));
    const char* gA = (const char*)(g_xh + (size_t)m0 * KDIM);
    const char* gB = (const char*)(g_wh + (size_t)n0 * KDIM);

    // ---- ldmatrix lane addressing ----
    uint32_t cks[4];
#pragma unroll
    for (int ks = 0; ks < 4; ks++)
        cks[ks] = (uint32_t)((((lane >> 4) * 16) + ks * 32) ^ ((lane & 7) << 4));
    const uint32_t arow = (uint32_t)((wm * 64 + (lane & 15)) * 128);
    const uint32_t brow = (uint32_t)((wn * 64 + (lane & 15)) * 128);

    float c[4][8][4];
#pragma unroll
    for (int mi = 0; mi < 4; mi++)
#pragma unroll
        for (int ni = 0; ni < 8; ni++)
#pragma unroll
            for (int r = 0; r < 4; r++) c[mi][ni][r] = 0.0f;

    auto issue_stage = [&](uint32_t ab, uint32_t bb, int kc) {
        const char* srcA = gA + (size_t)kc * (BK * 2);
        const char* srcB = gB + (size_t)kc * (BK * 2);
#pragma unroll
        for (int i = 0; i < 8; i++) {          // A: 128 rows x 8 segs / 128 thr
            int r = rbase + 16 * i;
            cp_async16(ab + (uint32_t)(r * 128) + swz,
                       srcA + (size_t)r * (KDIM * 2) + seg * 16);
        }
#pragma unroll
        for (int i = 0; i < 8; i++) {          // B: 128 rows x 8 segs / 128 thr
            int r = rbase + 16 * i;
            cp_async16(bb + (uint32_t)(r * 128) + swz,
                       srcB + (size_t)r * (KDIM * 2) + seg * 16);
        }
    };

    // ---- prologue: fill the ring ----
    issue_stage(sb + SM_A + 0 * A_STAGE, sb + SM_B + 0 * B_STAGE, 0); cp_commit();
    issue_stage(sb + SM_A + 1 * A_STAGE, sb + SM_B + 1 * B_STAGE, 1); cp_commit();

    // ---- incremental stage cursors (no per-iter modulo IMADs) ----
    // read cursor: stage of chunk k; write cursor: stage of chunk k+2 = (k+2)%3
    uint32_t rdA = sb + SM_A,                rdB = sb + SM_B;
    uint32_t wrA = sb + SM_A + 2 * A_STAGE,  wrB = sb + SM_B + 2 * B_STAGE;
    const uint32_t endA = sb + SM_A + STAGES * A_STAGE;
    const uint32_t endB = sb + SM_B + STAGES * B_STAGE;

    for (int k = 0; k < NCH; ++k) {
        cp_wait<1>();                          // stage k landed (2 pending -> 1)
        __syncthreads();                       // visibility + ring reuse safety

        const uint32_t ab = rdA + arow;
        const uint32_t bb = rdB + brow;

        // preload step-0 fragments, then kick next stage's cp.async
        uint32_t a[2][4][4], bf[2][4][4];
#pragma unroll
        for (int mi = 0; mi < 4; mi++) ldsm_x4(a[0][mi], ab + mi * 2048 + cks[0]);
#pragma unroll
        for (int nj = 0; nj < 4; nj++) ldsm_x4(bf[0][nj], bb + nj * 2048 + cks[0]);

        if (k + 2 < NCH) issue_stage(wrA, wrB, k + 2);
        cp_commit();                           // uniform group count

#pragma unroll
        for (int ks = 0; ks < 4; ks++) {
            const int cur = ks & 1, nxt = cur ^ 1;
            if (ks < 3) {
#pragma unroll
                for (int mi = 0; mi < 4; mi++)
                    ldsm_x4(a[nxt][mi], ab + mi * 2048 + cks[ks + 1]);
#pragma unroll
                for (int nj = 0; nj < 4; nj++)
                    ldsm_x4(bf[nxt][nj], bb + nj * 2048 + cks[ks + 1]);
            }
#pragma unroll
            for (int mi = 0; mi < 4; mi++)
#pragma unroll
                for (int nj = 0; nj < 4; nj++) {
                    mma16816(c[mi][2 * nj + 0], a[cur][mi], bf[cur][nj][0], bf[cur][nj][2]);
                    mma16816(c[mi][2 * nj + 1], a[cur][mi], bf[cur][nj][1], bf[cur][nj][3]);
                }
        }

        // advance cursors with wrap (ALU only)
        rdA += A_STAGE; if (rdA == endA) rdA = sb + SM_A;
        rdB += B_STAGE; if (rdB == endB) rdB = sb + SM_B;
        wrA += A_STAGE; if (wrA == endA) wrA = sb + SM_A;
        wrB += B_STAGE; if (wrB == endB) wrB = sb + SM_B;
    }

    // ---- epilogue: out = scale*acc + bias (streaming stores, keep L2 for fills)
    const float sc = *scale;
    const float* bsm = (const float*)(sm + SM_BIAS);
    const int qrow = lane >> 2;
    const int qcol = 2 * (lane & 3);
#pragma unroll
    for (int mi = 0; mi < 4; mi++) {
        const size_t mlo = (size_t)(m0 + wm * 64 + mi * 16 + qrow);
#pragma unroll
        for (int ni = 0; ni < 8; ni++) {
            const int nc = wn * 64 + ni * 8 + qcol;
            const float b0 = bsm[nc], b1 = bsm[nc + 1];
            float2 v0, v1;
            v0.x = fmaf(sc, c[mi][ni][0], b0);
            v0.y = fmaf(sc, c[mi][ni][1], b1);
            v1.x = fmaf(sc, c[mi][ni][2], b0);
            v1.y = fmaf(sc, c[mi][ni][3], b1);
            __stcs(reinterpret_cast<float2*>(out + mlo * NDIM + n0 + nc), v0);
            __stcs(reinterpret_cast<float2*>(out + (mlo + 8) * NDIM + n0 + nc), v1);
        }
    }
}

// ---------------------------------------------------------------- launch
extern "C" void kernel_launch(void* const* d_in, const int* in_sizes, int n_in,
                              void* d_out, int out_size) {
    const float* x     = (const float*)d_in[0];
    const int*   w4    = (const int*)d_in[1];
    const float* scale = (const float*)d_in[2];
    const float* zp    = (const float*)d_in[3];
    const float* bias  = (const float*)d_in[4];
    float* out = (float*)d_out;

    cudaFuncSetAttribute(gemm_hmma_kernel,
                         cudaFuncAttributeMaxDynamicSharedMemorySize, DYN_SMEM);

    {
        long n8 = (long)MDIM * KDIM / 8;
        cvt_x_kernel<<<(int)((n8 + 255) / 256), 256>>>(x);
    }
    {
        long n8 = (long)NDIM * KDIM / 8;
        cvt_w_kernel<<<(int)((n8 + 255) / 256), 256>>>(w4, zp);
    }
    gemm_hmma_kernel<<<GRID_M * GRID_N, NTHREADS, DYN_SMEM>>>(scale, bias, out);
}

// round 16
// speedup vs baseline: 1.1926x; 1.0849x over previous
#include <cuda_runtime.h>
#include <cuda_fp16.h>
#include <cstdint>

// Problem dims
static constexpr int MDIM = 8192;    // B*S
static constexpr int NDIM = 11008;   // OUT
static constexpr int KDIM = 4096;    // IN

// GEMM tiling (mma.sync path: harness assembles via .target sm_103 -> no tcgen05;
// cp.async.bulk + mbarrier are sm_90 baseline, NOT a-gated)
static constexpr int BM = 128;
static constexpr int BN = 128;
static constexpr int BK = 64;                 // 64 fp16 = 128B rows
static constexpr int NCH = KDIM / BK;         // 64 K-chunks
static constexpr int STAGES = 3;
static constexpr int NTHREADS = 128;          // 4 warps, warp tile 64x64

static constexpr int TILE_BYTES = 128 * 128;  // 16 KB: 128 rows x 128B (swizzled)
static constexpr int SM_A    = 0;             // 3 x 16KB
static constexpr int SM_B    = STAGES * TILE_BYTES;            // 49152
static constexpr int SM_BIAS = SM_B + STAGES * TILE_BYTES;     // 98304
static constexpr int SM_MB   = SM_BIAS + BN * 4;               // 98816 (3 x 8B mbars)
static constexpr int SM_END  = SM_MB + 64;
static constexpr int DYN_SMEM = SM_END + 1024;                 // ~97.5KB -> 2 CTAs/SM

static constexpr int GRID_M = MDIM / BM;      // 64
static constexpr int GRID_N = NDIM / BN;      // 86
static constexpr int GROUP_M = 8;             // L2 tile-swizzle panel height

// Pre-tiled, pre-swizzled fp16 copies:
//   g_xh[mtile][kchunk][16KB tile], g_wh[ntile][kchunk][16KB tile]
__device__ __half g_xh[(size_t)MDIM * KDIM];
__device__ __half g_wh[(size_t)NDIM * KDIM];

// ---------------------------------------------------------------- helpers
__device__ __forceinline__ uint32_t smem_u32(const void* p) {
    uint32_t a;
    asm("{ .reg .u64 t; cvta.to.shared.u64 t, %1; cvt.u32.u64 %0, t; }"
        : "=r"(a) : "l"(p));
    return a;
}

__device__ __forceinline__ uint32_t h2_bits(__half2 h) {
    union { __half2 h2; uint32_t u; } cvt;
    cvt.h2 = h;
    return cvt.u;
}

__device__ __forceinline__ void mbar_init(uint32_t addr, uint32_t cnt) {
    asm volatile("mbarrier.init.shared.b64 [%0], %1;" :: "r"(addr), "r"(cnt) : "memory");
}

__device__ __forceinline__ void mbar_expect_tx(uint32_t addr, uint32_t tx) {
    asm volatile("mbarrier.arrive.expect_tx.shared.b64 _, [%0], %1;"
                 :: "r"(addr), "r"(tx) : "memory");
}

__device__ __forceinline__ void mbar_wait(uint32_t addr, uint32_t phase) {
    asm volatile(
        "{\n\t"
        ".reg .pred P;\n\t"
        "WLOOP_%=:\n\t"
        "mbarrier.try_wait.parity.acquire.cta.shared::cta.b64 P, [%0], %1, 0x989680;\n\t"
        "@P bra WDONE_%=;\n\t"
        "bra WLOOP_%=;\n\t"
        "WDONE_%=:\n\t"
        "}"
        :: "r"(addr), "r"(phase) : "memory");
}

// One-instruction bulk copy GMEM -> SMEM, completion via mbarrier tx-count
__device__ __forceinline__ void bulk_ld(uint32_t dst, const void* src,
                                        uint32_t bytes, uint32_t mbar) {
    asm volatile(
        "cp.async.bulk.shared::cluster.global.mbarrier::complete_tx::bytes "
        "[%0], [%1], %2, [%3];"
        :: "r"(dst), "l"(src), "r"(bytes), "r"(mbar) : "memory");
}

__device__ __forceinline__ void ldsm_x4(uint32_t* r, uint32_t addr) {
    asm volatile("ldmatrix.sync.aligned.m8n8.x4.shared.b16 {%0,%1,%2,%3}, [%4];"
                 : "=r"(r[0]), "=r"(r[1]), "=r"(r[2]), "=r"(r[3])
                 : "r"(addr));
}

__device__ __forceinline__ void mma16816(float* c, const uint32_t* a,
                                         uint32_t b0, uint32_t b1) {
    asm volatile(
        "mma.sync.aligned.m16n8k16.row.col.f32.f16.f16.f32 "
        "{%0,%1,%2,%3}, {%4,%5,%6,%7}, {%8,%9}, {%0,%1,%2,%3};"
        : "+f"(c[0]), "+f"(c[1]), "+f"(c[2]), "+f"(c[3])
        : "r"(a[0]), "r"(a[1]), "r"(a[2]), "r"(a[3]), "r"(b0), "r"(b1));
}

// ---------------------------------------------------------------- conversion
// Write fp16 into pre-tiled layout: tile (row>>7, k>>6), inside 128x128B with
// SW swizzle (seg*16 ^ ((row&7)<<4)). Swizzle permutes 16B segs within one
// 128B line, so 8 consecutive threads still write one full 128B line.
__global__ void cvt_x_kernel(const float* __restrict__ x) {
    size_t i = (size_t)blockIdx.x * blockDim.x + threadIdx.x;   // seg index
    size_t nseg = (size_t)MDIM * (KDIM / 8);
    if (i < nseg) {
        int m  = (int)(i >> 9);           // 512 segs per row
        int sk = (int)(i & 511);
        int kc = sk >> 3;
        int seg = sk & 7;
        const float4* src = reinterpret_cast<const float4*>(x + (size_t)m * KDIM + sk * 8);
        float4 v0 = src[0], v1 = src[1];
        uint4 o;
        o.x = h2_bits(__floats2half2_rn(v0.x, v0.y));
        o.y = h2_bits(__floats2half2_rn(v0.z, v0.w));
        o.z = h2_bits(__floats2half2_rn(v1.x, v1.y));
        o.w = h2_bits(__floats2half2_rn(v1.z, v1.w));
        size_t tile = (size_t)(m >> 7) * NCH + kc;
        uint32_t off = (uint32_t)(((m & 127) * 128 + seg * 16) ^ ((m & 7) << 4));
        *reinterpret_cast<uint4*>(
            reinterpret_cast<char*>(g_xh) + tile * TILE_BYTES + off) = o;
    }
}

__global__ void cvt_w_kernel(const int* __restrict__ w4, const float* __restrict__ zp) {
    size_t i = (size_t)blockIdx.x * blockDim.x + threadIdx.x;   // seg index
    size_t nseg = (size_t)NDIM * (KDIM / 8);
    if (i < nseg) {
        int n  = (int)(i >> 9);
        int sk = (int)(i & 511);
        int kc = sk >> 3;
        int seg = sk & 7;
        const int4* src = reinterpret_cast<const int4*>(w4 + (size_t)n * KDIM + sk * 8);
        int4 q0 = src[0], q1 = src[1];
        int z = __float2int_rn(zp[0]);    // zero_point is an exact integer
        uint4 o;
        o.x = h2_bits(__floats2half2_rn((float)(q0.x - z), (float)(q0.y - z)));
        o.y = h2_bits(__floats2half2_rn((float)(q0.z - z), (float)(q0.w - z)));
        o.z = h2_bits(__floats2half2_rn((float)(q1.x - z), (float)(q1.y - z)));
        o.w = h2_bits(__floats2half2_rn((float)(q1.z - z), (float)(q1.w - z)));
        size_t tile = (size_t)(n >> 7) * NCH + kc;
        uint32_t off = (uint32_t)(((n & 127) * 128 + seg * 16) ^ ((n & 7) << 4));
        *reinterpret_cast<uint4*>(
            reinterpret_cast<char*>(g_wh) + tile * TILE_BYTES + off) = o;
    }
}

// ---------------------------------------------------------------- GEMM
__global__ void __launch_bounds__(NTHREADS, 2)
gemm_hmma_kernel(const float* __restrict__ scale, const float* __restrict__ bias,
                 float* __restrict__ out) {
    extern __shared__ char smem_raw[];
    char* sm = (char*)(((uintptr_t)smem_raw + 1023) & ~(uintptr_t)1023);
    uint32_t sb = smem_u32(sm);

    const int tid  = threadIdx.x;
    const int lane = tid & 31;
    const int wid  = tid >> 5;        // 0..3
    const int wm   = wid >> 1;        // 0..1  (64 M-rows per warp)
    const int wn   = wid & 1;         // 0..1  (64 N-cols per warp)

    // ---- CTA tile swizzle: GROUP_M-high panels for L2 reuse ----
    const int cid   = blockIdx.x;
    const int per_p = GROUP_M * GRID_N;
    const int panel = cid / per_p;
    const int rem   = cid - panel * per_p;
    const int bm    = panel * GROUP_M + (rem % GROUP_M);
    const int bn    = rem / GROUP_M;
    const int m0 = bm * BM;
    const int n0 = bn * BN;

    // contiguous 16KB tile streams for this CTA
    const char* gA = reinterpret_cast<const char*>(g_xh) + (size_t)bm * NCH * TILE_BYTES;
    const char* gB = reinterpret_cast<const char*>(g_wh) + (size_t)bn * NCH * TILE_BYTES;

    const uint32_t mb = sb + SM_MB;   // 3 mbarriers at mb, mb+8, mb+16

    if (tid == 0) {
        mbar_init(mb + 0, 1);
        mbar_init(mb + 8, 1);
        mbar_init(mb + 16, 1);
    }
    ((float*)(sm + SM_BIAS))[tid] = bias[n0 + tid];

    // ---- ldmatrix lane addressing (same swizzled tile layout as cvt wrote) ----
    uint32_t cks[4];
#pragma unroll
    for (int ks = 0; ks < 4; ks++)
        cks[ks] = (uint32_t)((((lane >> 4) * 16) + ks * 32) ^ ((lane & 7) << 4));
    const uint32_t arow = (uint32_t)((wm * 64 + (lane & 15)) * 128);
    const uint32_t brow = (uint32_t)((wn * 64 + (lane & 15)) * 128);

    float c[4][8][4];
#pragma unroll
    for (int mi = 0; mi < 4; mi++)
#pragma unroll
        for (int ni = 0; ni < 8; ni++)
#pragma unroll
            for (int r = 0; r < 4; r++) c[mi][ni][r] = 0.0f;

    __syncthreads();   // mbarrier init + bias visible

    // ---- prologue: fill stages 0,1 with chunks 0,1 ----
    if (tid == 0) {
        asm volatile("fence.proxy.async.shared::cta;" ::: "memory");
#pragma unroll
        for (int s = 0; s < 2; s++) {
            mbar_expect_tx(mb + 8 * s, 2 * TILE_BYTES);
            bulk_ld(sb + SM_A + s * TILE_BYTES, gA + (size_t)s * TILE_BYTES,
                    TILE_BYTES, mb + 8 * s);
            bulk_ld(sb + SM_B + s * TILE_BYTES, gB + (size_t)s * TILE_BYTES,
                    TILE_BYTES, mb + 8 * s);
        }
    }

    int s = 0, ph = 0;                 // consumer stage / parity cursors
    for (int k = 0; k < NCH; ++k) {
        if (k > 0) __syncthreads();    // all reads of chunk k-1 done (WAR for refill)
        if (tid == 0 && k + 2 < NCH) {
            const int s2 = (k + 2 < STAGES) ? (k + 2) : ((k + 2) - STAGES >= STAGES
                              ? (k + 2) % STAGES : (k + 2) - STAGES);
            const int st = (k + 2) % STAGES;
            (void)s2;
            asm volatile("fence.proxy.async.shared::cta;" ::: "memory");
            mbar_expect_tx(mb + 8 * st, 2 * TILE_BYTES);
            bulk_ld(sb + SM_A + st * TILE_BYTES, gA + (size_t)(k + 2) * TILE_BYTES,
                    TILE_BYTES, mb + 8 * st);
            bulk_ld(sb + SM_B + st * TILE_BYTES, gB + (size_t)(k + 2) * TILE_BYTES,
                    TILE_BYTES, mb + 8 * st);
        }

        mbar_wait(mb + 8 * s, (uint32_t)ph);   // chunk k resident

        const uint32_t ab = sb + SM_A + s * TILE_BYTES + arow;
        const uint32_t bb = sb + SM_B + s * TILE_BYTES + brow;

        // fragment double-buffer: LDSM for step s+1 overlaps MMAs of step s
        uint32_t a[2][4][4], bf[2][4][4];
#pragma unroll
        for (int mi = 0; mi < 4; mi++) ldsm_x4(a[0][mi], ab + mi * 2048 + cks[0]);
#pragma unroll
        for (int nj = 0; nj < 4; nj++) ldsm_x4(bf[0][nj], bb + nj * 2048 + cks[0]);

#pragma unroll
        for (int ks = 0; ks < 4; ks++) {
            const int cur = ks & 1, nxt = cur ^ 1;
            if (ks < 3) {
#pragma unroll
                for (int mi = 0; mi < 4; mi++)
                    ldsm_x4(a[nxt][mi], ab + mi * 2048 + cks[ks + 1]);
#pragma unroll
                for (int nj = 0; nj < 4; nj++)
                    ldsm_x4(bf[nxt][nj], bb + nj * 2048 + cks[ks + 1]);
            }
#pragma unroll
            for (int mi = 0; mi < 4; mi++)
#pragma unroll
                for (int nj = 0; nj < 4; nj++) {
                    mma16816(c[mi][2 * nj + 0], a[cur][mi], bf[cur][nj][0], bf[cur][nj][2]);
                    mma16816(c[mi][2 * nj + 1], a[cur][mi], bf[cur][nj][1], bf[cur][nj][3]);
                }
        }

        if (++s == STAGES) { s = 0; ph ^= 1; }
    }

    // ---- epilogue: out = scale*acc + bias (streaming stores) ----
    const float sc = *scale;
    const float* bsm = (const float*)(sm + SM_BIAS);
    const int qrow = lane >> 2;
    const int qcol = 2 * (lane & 3);
#pragma unroll
    for (int mi = 0; mi < 4; mi++) {
        const size_t mlo = (size_t)(m0 + wm * 64 + mi * 16 + qrow);
#pragma unroll
        for (int ni = 0; ni < 8; ni++) {
            const int nc = wn * 64 + ni * 8 + qcol;
            const float b0 = bsm[nc], b1 = bsm[nc + 1];
            float2 v0, v1;
            v0.x = fmaf(sc, c[mi][ni][0], b0);
            v0.y = fmaf(sc, c[mi][ni][1], b1);
            v1.x = fmaf(sc, c[mi][ni][2], b0);
            v1.y = fmaf(sc, c[mi][ni][3], b1);
            __stcs(reinterpret_cast<float2*>(out + mlo * NDIM + n0 + nc), v0);
            __stcs(reinterpret_cast<float2*>(out + (mlo + 8) * NDIM + n0 + nc), v1);
        }
    }

    __syncthreads();
    if (tid == 0) {
        asm volatile("mbarrier.inval.shared.b64 [%0];" :: "r"(mb + 0) : "memory");
        asm volatile("mbarrier.inval.shared.b64 [%0];" :: "r"(mb + 8) : "memory");
        asm volatile("mbarrier.inval.shared.b64 [%0];" :: "r"(mb + 16) : "memory");
    }
}

// ---------------------------------------------------------------- launch
extern "C" void kernel_launch(void* const* d_in, const int* in_sizes, int n_in,
                              void* d_out, int out_size) {
    const float* x     = (const float*)d_in[0];
    const int*   w4    = (const int*)d_in[1];
    const float* scale = (const float*)d_in[2];
    const float* zp    = (const float*)d_in[3];
    const float* bias  = (const float*)d_in[4];
    float* out = (float*)d_out;

    cudaFuncSetAttribute(gemm_hmma_kernel,
                         cudaFuncAttributeMaxDynamicSharedMemorySize, DYN_SMEM);

    {
        long nseg = (long)MDIM * KDIM / 8;
        cvt_x_kernel<<<(int)((nseg + 255) / 256), 256>>>(x);
    }
    {
        long nseg = (long)NDIM * KDIM / 8;
        cvt_w_kernel<<<(int)((nseg + 255) / 256), 256>>>(w4, zp);
    }
    gemm_hmma_kernel<<<GRID_M * GRID_N, NTHREADS, DYN_SMEM>>>(scale, bias, out);
}